// round 5
// baseline (speedup 1.0000x reference)
#include <cuda_runtime.h>

#define BB 4
#define LL 128
#define DD 256
#define TWO_D 512

// Gram scratch: [b][type][r][k], types: 0=0.5*Q.V^T(+mask), 1=0.5*V.V^T,
//                                        2=0.5*Q.Q^T(+mask), 3=0.5*V.Q^T
__device__ float g_gram[BB * 4 * LL * LL];

// ---------------------------------------------------------------------------
// Kernel 1: Gram matrices. grid (16, B): x = type*4 + rowquarter. 256 threads.
// Each block computes G[type][r0..r0+31][0..127] for one batch.
// ---------------------------------------------------------------------------
__global__ __launch_bounds__(256) void gram_kernel(
    const float* __restrict__ Q, const float* __restrict__ V,
    const int* __restrict__ mask)
{
    int b    = blockIdx.y;
    int type = blockIdx.x >> 2;
    int rq   = blockIdx.x & 3;
    const float* A  = ((type & 1) ? V : Q) + (size_t)b * LL * DD; // 0:Q 1:V 2:Q 3:V
    const float* Bm = ((type < 2) ? V : Q) + (size_t)b * LL * DD; // 0:V 1:V 2:Q 3:Q
    int r0 = rq * 32;

    __shared__ float sA[32 * 65];
    __shared__ float sB[128 * 65];

    float acc[4][4] = {};
    int t = threadIdx.x;

    for (int dc = 0; dc < DD; dc += 64) {
        // sB: 128 rows x 64 cols = 8192 elements -> 32 iterations of 256 threads
        #pragma unroll
        for (int u = 0; u < 32; u++) {
            int idx = t + u * 256;               // 0..8191
            int r = idx >> 6, d = idx & 63;
            sB[r * 65 + d] = Bm[r * DD + dc + d];
        }
        // sA: 32 rows x 64 cols = 2048 elements -> 8 iterations
        #pragma unroll
        for (int u = 0; u < 8; u++) {
            int idx = t + u * 256;               // 0..2047
            int r = idx >> 6, d = idx & 63;
            sA[r * 65 + d] = A[(r0 + r) * DD + dc + d];
        }
        __syncthreads();

        int rg = t >> 5;     // 0..7
        int kg = t & 31;     // 0..31
        const float* sAr = sA + rg * 4 * 65;
        const float* sBr = sB + kg * 4 * 65;
        #pragma unroll 8
        for (int d = 0; d < 64; d++) {
            float av[4], bv[4];
            #pragma unroll
            for (int a = 0; a < 4; a++) av[a] = sAr[a * 65 + d];
            #pragma unroll
            for (int c = 0; c < 4; c++) bv[c] = sBr[c * 65 + d];
            #pragma unroll
            for (int a = 0; a < 4; a++)
                #pragma unroll
                for (int c = 0; c < 4; c++)
                    acc[a][c] = fmaf(av[a], bv[c], acc[a][c]);
        }
        __syncthreads();
    }

    int rg = t >> 5, kg = t & 31;
    float* G = g_gram + (size_t)(b * 4 + type) * LL * LL;
    bool doMask = (type == 0) || (type == 2);
    #pragma unroll
    for (int a = 0; a < 4; a++) {
        #pragma unroll
        for (int c = 0; c < 4; c++) {
            int k = kg * 4 + c;
            float val = 0.5f * acc[a][c];
            if (doMask && mask[b * LL + k] == 0) val = -1e30f;
            G[(r0 + rg * 4 + a) * LL + k] = val;
        }
    }
}

// ---------------------------------------------------------------------------
// Kernel 2: attention + GEMM + LayerNorm.
// grid (2 j-tiles, 128 i, 4 b), 256 threads, dynamic smem.
// ---------------------------------------------------------------------------
#define SP_STRIDE 132
#define OFF_P    0
#define OFF_PQ   (64 * SP_STRIDE)          // 8448
#define OFF_T    (2 * 64 * SP_STRIDE)      // 16896
#define OFF_G1   (OFF_T + 128 * 64)        // 25088
#define OFF_G1Q  (OFF_G1 + 128)            // 25216
#define OFF_W    (OFF_G1Q + 128)           // 25344
#define OFF_BI   (OFF_W + 512)             // 25856
#define OFF_S1   (OFF_BI + 512)            // 26368
#define OFF_S2   (OFF_S1 + 64)             // 26432
#define OFF_MU   (OFF_S2 + 64)             // 26496
#define OFF_RS   (OFF_MU + 64)             // 26560
#define SMEM_FLOATS (OFF_RS + 64)          // 26624
#define SMEM_BYTES  (SMEM_FLOATS * 4)      // 106496

__global__ __launch_bounds__(256, 2) void attn_kernel(
    const float* __restrict__ Q, const float* __restrict__ V,
    const int* __restrict__ mask, const float* __restrict__ nw,
    const float* __restrict__ nb, float* __restrict__ out)
{
    int jt = blockIdx.x, i = blockIdx.y, b = blockIdx.z;
    int t  = threadIdx.x;
    int j0b = jt * 64;
    float* outBase = out + (((size_t)(b * LL + i)) * LL + j0b) * TWO_D;

    // Row mask on i: whole 64x512 region is zero.
    if (mask[b * LL + i] == 0) {
        float4 z = make_float4(0.f, 0.f, 0.f, 0.f);
        float4* o4 = (float4*)outBase;
        #pragma unroll 4
        for (int u = t; u < 64 * TWO_D / 4; u += 256) o4[u] = z;
        return;
    }

    extern __shared__ float sm[];
    float* sP   = sm + OFF_P;
    float* sPq  = sm + OFF_PQ;
    float* sT   = sm + OFF_T;
    float* sG1  = sm + OFF_G1;
    float* sG1q = sm + OFF_G1Q;
    float* sW   = sm + OFF_W;
    float* sBi  = sm + OFF_BI;
    float* sS1  = sm + OFF_S1;
    float* sS2  = sm + OFF_S2;
    float* sMu  = sm + OFF_MU;
    float* sRs  = sm + OFF_RS;

    const float* G   = g_gram + (size_t)b * 4 * LL * LL;
    const float* G2  = G + 1 * LL * LL;
    const float* G2q = G + 3 * LL * LL;

    if (t < 128) {
        sG1[t]  = G[i * LL + t];                 // masked 0.5*q_i . v_k
        sG1q[t] = G[2 * LL * LL + i * LL + t];   // masked 0.5*q_i . q_k
    }
    for (int u = t; u < 512; u += 256) { sW[u] = nw[u]; sBi[u] = nb[u]; }
    if (t < 64) { sS1[t] = 0.f; sS2[t] = 0.f; }
    __syncthreads();

    // ---- Phase A: dual softmax per j row -> P, Pq in smem ----
    int warp = t >> 5, lane = t & 31;
    for (int jj = warp; jj < 64; jj += 8) {
        int j = j0b + jj;
        {
            const float* r = G2 + j * LL;
            float s0 = sG1[lane]      + r[lane];
            float s1 = sG1[lane + 32] + r[lane + 32];
            float s2 = sG1[lane + 64] + r[lane + 64];
            float s3 = sG1[lane + 96] + r[lane + 96];
            float m = fmaxf(fmaxf(s0, s1), fmaxf(s2, s3));
            #pragma unroll
            for (int o = 16; o; o >>= 1) m = fmaxf(m, __shfl_xor_sync(0xffffffffu, m, o));
            float e0 = __expf(s0 - m), e1 = __expf(s1 - m);
            float e2 = __expf(s2 - m), e3 = __expf(s3 - m);
            float su = e0 + e1 + e2 + e3;
            #pragma unroll
            for (int o = 16; o; o >>= 1) su += __shfl_xor_sync(0xffffffffu, su, o);
            float inv = 1.0f / su;
            float* pr = sP + jj * SP_STRIDE;
            pr[lane] = e0 * inv; pr[lane + 32] = e1 * inv;
            pr[lane + 64] = e2 * inv; pr[lane + 96] = e3 * inv;
        }
        {
            const float* r = G2q + j * LL;
            float s0 = sG1q[lane]      + r[lane];
            float s1 = sG1q[lane + 32] + r[lane + 32];
            float s2 = sG1q[lane + 64] + r[lane + 64];
            float s3 = sG1q[lane + 96] + r[lane + 96];
            float m = fmaxf(fmaxf(s0, s1), fmaxf(s2, s3));
            #pragma unroll
            for (int o = 16; o; o >>= 1) m = fmaxf(m, __shfl_xor_sync(0xffffffffu, m, o));
            float e0 = __expf(s0 - m), e1 = __expf(s1 - m);
            float e2 = __expf(s2 - m), e3 = __expf(s3 - m);
            float su = e0 + e1 + e2 + e3;
            #pragma unroll
            for (int o = 16; o; o >>= 1) su += __shfl_xor_sync(0xffffffffu, su, o);
            float inv = 1.0f / su;
            float* pr = sPq + jj * SP_STRIDE;
            pr[lane] = e0 * inv; pr[lane + 32] = e1 * inv;
            pr[lane + 64] = e2 * inv; pr[lane + 96] = e3 * inv;
        }
    }
    __syncthreads();

    // ---- Phase B: out[j, d] = P @ V  /  Pq @ Q, d-tiles of 64 ----
    int jg = t >> 4;   // 0..15 -> j microtile base jg*4
    int dg = t & 15;   // 0..15 -> d microtile base dg*4
    const float* QB = Q + (size_t)b * LL * DD;
    const float* VB = V + (size_t)b * LL * DD;

    #pragma unroll 1
    for (int tile = 0; tile < 8; tile++) {
        int qside = tile >> 2;
        const float* src = qside ? QB : VB;
        int dbase = (tile & 3) * 64;
        #pragma unroll
        for (int u = 0; u < 8; u++) {
            int idx = t + u * 256;               // float4 index 0..2047
            int k = idx >> 4, c4 = idx & 15;
            *(float4*)&sT[k * 64 + c4 * 4] =
                *(const float4*)&src[k * DD + dbase + c4 * 4];
        }
        __syncthreads();

        const float* P   = qside ? sPq : sP;
        const float* Pr0 = P + jg * 4 * SP_STRIDE;
        float acc[4][4] = {};
        #pragma unroll 4
        for (int k = 0; k < 128; k += 4) {
            float pk[4][4];   // [a][kk]
            float tk[4][4];   // [kk][c]
            #pragma unroll
            for (int a = 0; a < 4; a++)
                *(float4*)pk[a] = *(const float4*)&Pr0[a * SP_STRIDE + k];
            #pragma unroll
            for (int kk = 0; kk < 4; kk++)
                *(float4*)tk[kk] = *(const float4*)&sT[(k + kk) * 64 + dg * 4];
            #pragma unroll
            for (int a = 0; a < 4; a++)
                #pragma unroll
                for (int kk = 0; kk < 4; kk++)
                    #pragma unroll
                    for (int c = 0; c < 4; c++)
                        acc[a][c] = fmaf(pk[a][kk], tk[kk][c], acc[a][c]);
        }

        int dglob = qside * 256 + dbase + dg * 4;
        #pragma unroll
        for (int a = 0; a < 4; a++) {
            int j = jg * 4 + a;
            float4 r = make_float4(acc[a][0], acc[a][1], acc[a][2], acc[a][3]);
            *(float4*)&outBase[(size_t)j * TWO_D + dglob] = r;
            atomicAdd(&sS1[j], r.x + r.y + r.z + r.w);
            atomicAdd(&sS2[j], r.x * r.x + r.y * r.y + r.z * r.z + r.w * r.w);
        }
        __syncthreads();
    }

    // ---- Phase C: LayerNorm in place (own region is L2-hot) ----
    if (t < 64) {
        float mu  = sS1[t] * (1.0f / 512.0f);
        float var = sS2[t] * (1.0f / 512.0f) - mu * mu;
        sMu[t] = mu;
        sRs[t] = rsqrtf(var + 1e-5f);
    }
    __syncthreads();

    int jr = t >> 2, part = t & 3;
    float mu = sMu[jr], rs = sRs[jr];
    float* orow = outBase + (size_t)jr * TWO_D;
    #pragma unroll 8
    for (int it = 0; it < 32; it++) {
        int idx4 = it * 4 + part;       // 0..127
        int d = idx4 * 4;
        float4 x = *(float4*)&orow[d];
        x.x = (x.x - mu) * rs * sW[d + 0] + sBi[d + 0];
        x.y = (x.y - mu) * rs * sW[d + 1] + sBi[d + 1];
        x.z = (x.z - mu) * rs * sW[d + 2] + sBi[d + 2];
        x.w = (x.w - mu) * rs * sW[d + 3] + sBi[d + 3];
        *(float4*)&orow[d] = x;
    }
    // mask[b,i] == 1 guaranteed here, so no final mask multiply needed.
}

// ---------------------------------------------------------------------------
extern "C" void kernel_launch(void* const* d_in, const int* in_sizes, int n_in,
                              void* d_out, int out_size)
{
    const float* q    = (const float*)d_in[0];
    const float* v    = (const float*)d_in[1];
    const int*   mask = (const int*)d_in[2];
    const float* nw   = (const float*)d_in[3];
    const float* nb   = (const float*)d_in[4];
    float* out = (float*)d_out;

    gram_kernel<<<dim3(16, BB), 256>>>(q, v, mask);

    cudaFuncSetAttribute(attn_kernel,
                         cudaFuncAttributeMaxDynamicSharedMemorySize, SMEM_BYTES);
    attn_kernel<<<dim3(2, LL, BB), 256, SMEM_BYTES>>>(q, v, mask, nw, nb, out);
}

// round 7
// speedup vs baseline: 1.3588x; 1.3588x over previous
#include <cuda_runtime.h>

#define BB 4
#define LL 128
#define DD 256
#define TWO_D 512

// Gram scratch: [b][type][r][k], types: 0=0.5*Q.V^T(+mask), 1=0.5*V.V^T,
//                                        2=0.5*Q.Q^T(+mask), 3=0.5*V.Q^T
__device__ float g_gram[BB * 4 * LL * LL];

// ---------------------------------------------------------------------------
// Kernel 1: Gram matrices. grid (16, B). 256 threads.
// ---------------------------------------------------------------------------
__global__ __launch_bounds__(256) void gram_kernel(
    const float* __restrict__ Q, const float* __restrict__ V,
    const int* __restrict__ mask)
{
    int b    = blockIdx.y;
    int type = blockIdx.x >> 2;
    int rq   = blockIdx.x & 3;
    const float* A  = ((type & 1) ? V : Q) + (size_t)b * LL * DD;
    const float* Bm = ((type < 2) ? V : Q) + (size_t)b * LL * DD;
    int r0 = rq * 32;

    __shared__ float sA[32 * 65];
    __shared__ float sB[128 * 65];

    float acc[4][4] = {};
    int t = threadIdx.x;

    for (int dc = 0; dc < DD; dc += 64) {
        #pragma unroll
        for (int u = 0; u < 32; u++) {
            int idx = t + u * 256;
            int r = idx >> 6, d = idx & 63;
            sB[r * 65 + d] = Bm[r * DD + dc + d];
        }
        #pragma unroll
        for (int u = 0; u < 8; u++) {
            int idx = t + u * 256;
            int r = idx >> 6, d = idx & 63;
            sA[r * 65 + d] = A[(r0 + r) * DD + dc + d];
        }
        __syncthreads();

        int rg = t >> 5;
        int kg = t & 31;
        const float* sAr = sA + rg * 4 * 65;
        const float* sBr = sB + kg * 4 * 65;
        #pragma unroll 8
        for (int d = 0; d < 64; d++) {
            float av[4], bv[4];
            #pragma unroll
            for (int a = 0; a < 4; a++) av[a] = sAr[a * 65 + d];
            #pragma unroll
            for (int c = 0; c < 4; c++) bv[c] = sBr[c * 65 + d];
            #pragma unroll
            for (int a = 0; a < 4; a++)
                #pragma unroll
                for (int c = 0; c < 4; c++)
                    acc[a][c] = fmaf(av[a], bv[c], acc[a][c]);
        }
        __syncthreads();
    }

    int rg = t >> 5, kg = t & 31;
    float* G = g_gram + (size_t)(b * 4 + type) * LL * LL;
    bool doMask = (type == 0) || (type == 2);
    #pragma unroll
    for (int a = 0; a < 4; a++) {
        #pragma unroll
        for (int c = 0; c < 4; c++) {
            int k = kg * 4 + c;
            float val = 0.5f * acc[a][c];
            if (doMask && mask[b * LL + k] == 0) val = -1e30f;
            G[(r0 + rg * 4 + a) * LL + k] = val;
        }
    }
}

// ---------------------------------------------------------------------------
// Kernel 2: attention + GEMM + LayerNorm.
// grid (2 j-tiles, 128 i, 4 b), 512 threads, dynamic smem.
// ---------------------------------------------------------------------------
#define NT 512
#define SP_STRIDE 132
#define OFF_P    0
#define OFF_PQ   (64 * SP_STRIDE)          // 8448
#define OFF_T    (2 * 64 * SP_STRIDE)      // 16896  (128*64 = 8192 floats)
#define OFF_G1   (OFF_T + 128 * 64)        // 25088
#define OFF_G1Q  (OFF_G1 + 128)            // 25216
#define OFF_W    (OFF_G1Q + 128)           // 25344
#define OFF_BI   (OFF_W + 512)             // 25856
#define OFF_MU   (OFF_BI + 512)            // 26368
#define OFF_RS   (OFF_MU + 64)             // 26432
#define SMEM_FLOATS (OFF_RS + 64)          // 26496
#define SMEM_BYTES  (SMEM_FLOATS * 4)      // 105984

__global__ __launch_bounds__(NT, 2) void attn_kernel(
    const float* __restrict__ Q, const float* __restrict__ V,
    const int* __restrict__ mask, const float* __restrict__ nw,
    const float* __restrict__ nb, float* __restrict__ out)
{
    int jt = blockIdx.x, i = blockIdx.y, b = blockIdx.z;
    int t  = threadIdx.x;
    int j0b = jt * 64;
    float* outBase = out + (((size_t)(b * LL + i)) * LL + j0b) * TWO_D;

    // Row mask on i: whole 64x512 region is zero.
    if (mask[b * LL + i] == 0) {
        float4 z = make_float4(0.f, 0.f, 0.f, 0.f);
        float4* o4 = (float4*)outBase;
        #pragma unroll
        for (int u = 0; u < 16; u++) o4[t + u * NT] = z;
        return;
    }

    extern __shared__ float sm[];
    float* sP   = sm + OFF_P;
    float* sPq  = sm + OFF_PQ;
    float* sT   = sm + OFF_T;
    float* sG1  = sm + OFF_G1;
    float* sG1q = sm + OFF_G1Q;
    float* sW   = sm + OFF_W;
    float* sBi  = sm + OFF_BI;
    float* sMu  = sm + OFF_MU;
    float* sRs  = sm + OFF_RS;

    const float* G   = g_gram + (size_t)b * 4 * LL * LL;
    const float* G2  = G + 1 * LL * LL;
    const float* G2q = G + 3 * LL * LL;

    if (t < 128) {
        sG1[t]  = G[i * LL + t];                 // masked 0.5*q_i . v_k
        sG1q[t] = G[2 * LL * LL + i * LL + t];   // masked 0.5*q_i . q_k
    }
    // LayerNorm weight/bias: full block, strided (512 threads x 1 each).
    sW[t]  = nw[t];
    sBi[t] = nb[t];
    __syncthreads();

    // ---- Phase A: dual softmax per j row -> P, Pq in smem ----
    int warp = t >> 5, lane = t & 31;
    for (int jj = warp; jj < 64; jj += 16) {
        int j = j0b + jj;
        {
            const float* r = G2 + j * LL;
            float s0 = sG1[lane]      + r[lane];
            float s1 = sG1[lane + 32] + r[lane + 32];
            float s2 = sG1[lane + 64] + r[lane + 64];
            float s3 = sG1[lane + 96] + r[lane + 96];
            float m = fmaxf(fmaxf(s0, s1), fmaxf(s2, s3));
            #pragma unroll
            for (int o = 16; o; o >>= 1) m = fmaxf(m, __shfl_xor_sync(0xffffffffu, m, o));
            float e0 = __expf(s0 - m), e1 = __expf(s1 - m);
            float e2 = __expf(s2 - m), e3 = __expf(s3 - m);
            float su = e0 + e1 + e2 + e3;
            #pragma unroll
            for (int o = 16; o; o >>= 1) su += __shfl_xor_sync(0xffffffffu, su, o);
            float inv = 1.0f / su;
            float* pr = sP + jj * SP_STRIDE;
            pr[lane] = e0 * inv; pr[lane + 32] = e1 * inv;
            pr[lane + 64] = e2 * inv; pr[lane + 96] = e3 * inv;
        }
        {
            const float* r = G2q + j * LL;
            float s0 = sG1q[lane]      + r[lane];
            float s1 = sG1q[lane + 32] + r[lane + 32];
            float s2 = sG1q[lane + 64] + r[lane + 64];
            float s3 = sG1q[lane + 96] + r[lane + 96];
            float m = fmaxf(fmaxf(s0, s1), fmaxf(s2, s3));
            #pragma unroll
            for (int o = 16; o; o >>= 1) m = fmaxf(m, __shfl_xor_sync(0xffffffffu, m, o));
            float e0 = __expf(s0 - m), e1 = __expf(s1 - m);
            float e2 = __expf(s2 - m), e3 = __expf(s3 - m);
            float su = e0 + e1 + e2 + e3;
            #pragma unroll
            for (int o = 16; o; o >>= 1) su += __shfl_xor_sync(0xffffffffu, su, o);
            float inv = 1.0f / su;
            float* pr = sPq + jj * SP_STRIDE;
            pr[lane] = e0 * inv; pr[lane + 32] = e1 * inv;
            pr[lane + 64] = e2 * inv; pr[lane + 96] = e3 * inv;
        }
    }
    __syncthreads();

    // ---- Phase B: out[j, d] = P @ V / Pq @ Q, d-tiles of 64 ----
    // 512 threads: jg = warp (0..15) -> 4 j rows; dg = lane (0..31) -> 2 d cols.
    // P loads are warp-uniform broadcasts; T loads are LDS.64.
    int jg = warp;       // 0..15
    int dg = lane;       // 0..31
    const float* QB = Q + (size_t)b * LL * DD;
    const float* VB = V + (size_t)b * LL * DD;

    float ls1[4] = {0.f, 0.f, 0.f, 0.f};   // LN sum per j row
    float ls2[4] = {0.f, 0.f, 0.f, 0.f};   // LN sum of squares per j row

    #pragma unroll 1
    for (int tile = 0; tile < 8; tile++) {
        int qside = tile >> 2;
        const float* src = qside ? QB : VB;
        int dbase = (tile & 3) * 64;
        #pragma unroll
        for (int u = 0; u < 4; u++) {
            int idx = t + u * NT;                // float4 index 0..2047
            int k = idx >> 4, c4 = idx & 15;
            *(float4*)&sT[k * 64 + c4 * 4] =
                *(const float4*)&src[k * DD + dbase + c4 * 4];
        }
        __syncthreads();

        const float* P   = qside ? sPq : sP;
        const float* Pr0 = P + jg * 4 * SP_STRIDE;
        float acc[4][2] = {};
        #pragma unroll 4
        for (int k = 0; k < 128; k += 4) {
            float pk[4][4];   // [a][kk]  (broadcast loads)
            float tk[4][2];   // [kk][c]
            #pragma unroll
            for (int a = 0; a < 4; a++)
                *(float4*)pk[a] = *(const float4*)&Pr0[a * SP_STRIDE + k];
            #pragma unroll
            for (int kk = 0; kk < 4; kk++)
                *(float2*)tk[kk] = *(const float2*)&sT[(k + kk) * 64 + dg * 2];
            #pragma unroll
            for (int a = 0; a < 4; a++)
                #pragma unroll
                for (int kk = 0; kk < 4; kk++) {
                    acc[a][0] = fmaf(pk[a][kk], tk[kk][0], acc[a][0]);
                    acc[a][1] = fmaf(pk[a][kk], tk[kk][1], acc[a][1]);
                }
        }

        int dglob = qside * 256 + dbase + dg * 2;
        #pragma unroll
        for (int a = 0; a < 4; a++) {
            int j = jg * 4 + a;
            float x = acc[a][0], y = acc[a][1];
            *(float2*)&outBase[(size_t)j * TWO_D + dglob] = make_float2(x, y);
            ls1[a] += x + y;
            ls2[a] = fmaf(x, x, fmaf(y, y, ls2[a]));
        }
        __syncthreads();
    }

    // ---- LN stats reduction (reuse sT as scratch; no atomics) ----
    // red1[j][dg] at sT[j*33 + dg], red2 at sT[64*33 + j*33 + dg]
    {
        float* red1 = sT;
        float* red2 = sT + 64 * 33;
        #pragma unroll
        for (int a = 0; a < 4; a++) {
            int j = jg * 4 + a;
            red1[j * 33 + dg] = ls1[a];
            red2[j * 33 + dg] = ls2[a];
        }
        __syncthreads();
        if (t < 64) {
            float s1 = 0.f, s2 = 0.f;
            const float* r1 = red1 + t * 33;
            const float* r2 = red2 + t * 33;
            #pragma unroll
            for (int u = 0; u < 32; u++) { s1 += r1[u]; s2 += r2[u]; }
            float mu  = s1 * (1.0f / 512.0f);
            float var = s2 * (1.0f / 512.0f) - mu * mu;
            sMu[t] = mu;
            sRs[t] = rsqrtf(var + 1e-5f);
        }
        __syncthreads();
    }

    // ---- Phase C: LayerNorm in place (region is L2-hot) ----
    // 64 rows x 128 float4; 512 threads -> row = t>>3, 16 float4 per thread.
    int jr = t >> 3, part = t & 7;
    float mu = sMu[jr], rs = sRs[jr];
    float* orow = outBase + (size_t)jr * TWO_D;
    #pragma unroll 4
    for (int it = 0; it < 16; it++) {
        int idx4 = it * 8 + part;       // 0..127
        int d = idx4 * 4;
        float4 x = *(float4*)&orow[d];
        x.x = (x.x - mu) * rs * sW[d + 0] + sBi[d + 0];
        x.y = (x.y - mu) * rs * sW[d + 1] + sBi[d + 1];
        x.z = (x.z - mu) * rs * sW[d + 2] + sBi[d + 2];
        x.w = (x.w - mu) * rs * sW[d + 3] + sBi[d + 3];
        *(float4*)&orow[d] = x;
    }
    // mask[b,i] == 1 guaranteed here, so no final mask multiply needed.
}

// ---------------------------------------------------------------------------
extern "C" void kernel_launch(void* const* d_in, const int* in_sizes, int n_in,
                              void* d_out, int out_size)
{
    const float* q    = (const float*)d_in[0];
    const float* v    = (const float*)d_in[1];
    const int*   mask = (const int*)d_in[2];
    const float* nw   = (const float*)d_in[3];
    const float* nb   = (const float*)d_in[4];
    float* out = (float*)d_out;

    gram_kernel<<<dim3(16, BB), 256>>>(q, v, mask);

    cudaFuncSetAttribute(attn_kernel,
                         cudaFuncAttributeMaxDynamicSharedMemorySize, SMEM_BYTES);
    attn_kernel<<<dim3(2, LL, BB), NT, SMEM_BYTES>>>(q, v, mask, nw, nb, out);
}

// round 8
// speedup vs baseline: 1.3617x; 1.0022x over previous
#include <cuda_runtime.h>

#define BB 4
#define LL 128
#define DD 256
#define TWO_D 512

// Gram scratch: [b][type][r][k], types: 0=0.5*Q.V^T(+mask), 1=0.5*V.V^T,
//                                        2=0.5*Q.Q^T(+mask), 3=0.5*V.Q^T
__device__ float g_gram[BB * 4 * LL * LL];

// Mask compaction lists: pair = b*128 + i
__device__ int g_active[BB * LL];
__device__ int g_inactive[BB * LL];
__device__ int g_nactive;

// ---------------------------------------------------------------------------
// Kernel 0: compact mask into active/inactive pair lists. 1 block, 512 thr.
// ---------------------------------------------------------------------------
__global__ __launch_bounds__(BB * LL) void compact_kernel(
    const int* __restrict__ mask)
{
    __shared__ int cA, cI;
    int t = threadIdx.x;
    if (t == 0) { cA = 0; cI = 0; }
    __syncthreads();
    if (mask[t]) { int p = atomicAdd(&cA, 1); g_active[p] = t; }
    else         { int p = atomicAdd(&cI, 1); g_inactive[p] = t; }
    __syncthreads();
    if (t == 0) g_nactive = cA;
}

// ---------------------------------------------------------------------------
// Kernel 1: Gram matrices. grid (16, B). 256 threads.
// ---------------------------------------------------------------------------
__global__ __launch_bounds__(256) void gram_kernel(
    const float* __restrict__ Q, const float* __restrict__ V,
    const int* __restrict__ mask)
{
    int b    = blockIdx.y;
    int type = blockIdx.x >> 2;
    int rq   = blockIdx.x & 3;
    const float* A  = ((type & 1) ? V : Q) + (size_t)b * LL * DD;
    const float* Bm = ((type < 2) ? V : Q) + (size_t)b * LL * DD;
    int r0 = rq * 32;

    __shared__ float sA[32 * 65];
    __shared__ float sB[128 * 65];

    float acc[4][4] = {};
    int t = threadIdx.x;

    for (int dc = 0; dc < DD; dc += 64) {
        #pragma unroll
        for (int u = 0; u < 32; u++) {
            int idx = t + u * 256;
            int r = idx >> 6, d = idx & 63;
            sB[r * 65 + d] = Bm[r * DD + dc + d];
        }
        #pragma unroll
        for (int u = 0; u < 8; u++) {
            int idx = t + u * 256;
            int r = idx >> 6, d = idx & 63;
            sA[r * 65 + d] = A[(r0 + r) * DD + dc + d];
        }
        __syncthreads();

        int rg = t >> 5;
        int kg = t & 31;
        const float* sAr = sA + rg * 4 * 65;
        const float* sBr = sB + kg * 4 * 65;
        #pragma unroll 8
        for (int d = 0; d < 64; d++) {
            float av[4], bv[4];
            #pragma unroll
            for (int a = 0; a < 4; a++) av[a] = sAr[a * 65 + d];
            #pragma unroll
            for (int c = 0; c < 4; c++) bv[c] = sBr[c * 65 + d];
            #pragma unroll
            for (int a = 0; a < 4; a++)
                #pragma unroll
                for (int c = 0; c < 4; c++)
                    acc[a][c] = fmaf(av[a], bv[c], acc[a][c]);
        }
        __syncthreads();
    }

    int rg = t >> 5, kg = t & 31;
    float* G = g_gram + (size_t)(b * 4 + type) * LL * LL;
    bool doMask = (type == 0) || (type == 2);
    #pragma unroll
    for (int a = 0; a < 4; a++) {
        #pragma unroll
        for (int c = 0; c < 4; c++) {
            int k = kg * 4 + c;
            float val = 0.5f * acc[a][c];
            if (doMask && mask[b * LL + k] == 0) val = -1e30f;
            G[(r0 + rg * 4 + a) * LL + k] = val;
        }
    }
}

// ---------------------------------------------------------------------------
// Kernel 2: attention + GEMM + LayerNorm. One block per (b,i), 512 threads.
// j-tile = 128 (full). Double-buffered T tiles via register prefetch.
// ---------------------------------------------------------------------------
#define NT 512
#define SP_STRIDE 132
#define OFF_P    0
#define OFF_PQ   (128 * SP_STRIDE)             // 16896
#define OFF_T    (2 * 128 * SP_STRIDE)         // 33792  (2 buffers x 8192)
#define OFF_G1   (OFF_T + 2 * 128 * 64)        // 50176
#define OFF_G1Q  (OFF_G1 + 128)                // 50304
#define OFF_W    (OFF_G1Q + 128)               // 50432
#define OFF_BI   (OFF_W + 512)                 // 50944
#define OFF_MU   (OFF_BI + 512)                // 51456
#define OFF_RS   (OFF_MU + 128)                // 51584
#define SMEM_FLOATS (OFF_RS + 128)             // 51712
#define SMEM_BYTES  (SMEM_FLOATS * 4)          // 206848

__global__ __launch_bounds__(NT) void attn_kernel(
    const float* __restrict__ Q, const float* __restrict__ V,
    const float* __restrict__ nw, const float* __restrict__ nb,
    float* __restrict__ out)
{
    int bid = blockIdx.x;
    int t   = threadIdx.x;
    int nA  = g_nactive;
    bool active = (bid < nA);
    int pair = active ? g_active[bid] : g_inactive[bid - nA];
    int b = pair >> 7, i = pair & 127;
    float* outBase = out + ((size_t)(b * LL + i)) * LL * TWO_D; // [128 j][512 d]

    if (!active) {
        float4 z = make_float4(0.f, 0.f, 0.f, 0.f);
        float4* o4 = (float4*)outBase;
        #pragma unroll
        for (int u = 0; u < 32; u++) o4[t + u * NT] = z;
        return;
    }

    extern __shared__ float sm[];
    float* sP   = sm + OFF_P;
    float* sPq  = sm + OFF_PQ;
    float* sT   = sm + OFF_T;
    float* sG1  = sm + OFF_G1;
    float* sG1q = sm + OFF_G1Q;
    float* sW   = sm + OFF_W;
    float* sBi  = sm + OFF_BI;
    float* sMu  = sm + OFF_MU;
    float* sRs  = sm + OFF_RS;

    const float* G   = g_gram + (size_t)b * 4 * LL * LL;
    const float* G2  = G + 1 * LL * LL;   // 0.5*V.V^T
    const float* G2q = G + 3 * LL * LL;   // 0.5*V.Q^T

    const float* QB = Q + (size_t)b * LL * DD;
    const float* VB = V + (size_t)b * LL * DD;

    if (t < 128) {
        sG1[t]  = G[i * LL + t];                 // masked 0.5*q_i . v_k
        sG1q[t] = G[2 * LL * LL + i * LL + t];   // masked 0.5*q_i . q_k
    }
    sW[t]  = nw[t];
    sBi[t] = nb[t];

    // ---- Prefetch T tile 0 into registers (overlaps with phase A) ----
    float4 pf[4];
    {
        // tile 0: V side, dbase 0
        #pragma unroll
        for (int u = 0; u < 4; u++) {
            int idx = t + u * NT;                // 0..2047 (float4 slots)
            int k = idx >> 4, c4 = idx & 15;
            pf[u] = *(const float4*)&VB[k * DD + c4 * 4];
        }
    }
    __syncthreads();

    // ---- Phase A: dual softmax per j row -> P, Pq in smem ----
    int warp = t >> 5, lane = t & 31;
    for (int jj = warp; jj < 128; jj += 16) {
        {
            const float* r = G2 + jj * LL;
            float s0 = sG1[lane]      + r[lane];
            float s1 = sG1[lane + 32] + r[lane + 32];
            float s2 = sG1[lane + 64] + r[lane + 64];
            float s3 = sG1[lane + 96] + r[lane + 96];
            float m = fmaxf(fmaxf(s0, s1), fmaxf(s2, s3));
            #pragma unroll
            for (int o = 16; o; o >>= 1) m = fmaxf(m, __shfl_xor_sync(0xffffffffu, m, o));
            float e0 = __expf(s0 - m), e1 = __expf(s1 - m);
            float e2 = __expf(s2 - m), e3 = __expf(s3 - m);
            float su = e0 + e1 + e2 + e3;
            #pragma unroll
            for (int o = 16; o; o >>= 1) su += __shfl_xor_sync(0xffffffffu, su, o);
            float inv = 1.0f / su;
            float* pr = sP + jj * SP_STRIDE;
            pr[lane] = e0 * inv; pr[lane + 32] = e1 * inv;
            pr[lane + 64] = e2 * inv; pr[lane + 96] = e3 * inv;
        }
        {
            const float* r = G2q + jj * LL;
            float s0 = sG1q[lane]      + r[lane];
            float s1 = sG1q[lane + 32] + r[lane + 32];
            float s2 = sG1q[lane + 64] + r[lane + 64];
            float s3 = sG1q[lane + 96] + r[lane + 96];
            float m = fmaxf(fmaxf(s0, s1), fmaxf(s2, s3));
            #pragma unroll
            for (int o = 16; o; o >>= 1) m = fmaxf(m, __shfl_xor_sync(0xffffffffu, m, o));
            float e0 = __expf(s0 - m), e1 = __expf(s1 - m);
            float e2 = __expf(s2 - m), e3 = __expf(s3 - m);
            float su = e0 + e1 + e2 + e3;
            #pragma unroll
            for (int o = 16; o; o >>= 1) su += __shfl_xor_sync(0xffffffffu, su, o);
            float inv = 1.0f / su;
            float* pr = sPq + jj * SP_STRIDE;
            pr[lane] = e0 * inv; pr[lane + 32] = e1 * inv;
            pr[lane + 64] = e2 * inv; pr[lane + 96] = e3 * inv;
        }
    }

    // Store prefetched tile 0 into buffer 0.
    {
        float* buf0 = sT;
        #pragma unroll
        for (int u = 0; u < 4; u++) {
            int idx = t + u * NT;
            int k = idx >> 4, c4 = idx & 15;
            *(float4*)&buf0[k * 64 + c4 * 4] = pf[u];
        }
    }
    __syncthreads();

    // ---- Phase B: out[j, d] = P @ V / Pq @ Q, 8 d-tiles of 64 ----
    // warp jg handles 8 j rows (jg*8..+7); lane dg handles 2 d cols.
    int jg = warp;
    int dg = lane;

    float ls1[8] = {}, ls2[8] = {};

    #pragma unroll 1
    for (int tile = 0; tile < 8; tile++) {
        // Prefetch next tile into registers (global loads in flight).
        if (tile < 7) {
            int nxt = tile + 1;
            const float* src = (nxt >> 2) ? QB : VB;
            int dbase = (nxt & 3) * 64;
            #pragma unroll
            for (int u = 0; u < 4; u++) {
                int idx = t + u * NT;
                int k = idx >> 4, c4 = idx & 15;
                pf[u] = *(const float4*)&src[k * DD + dbase + c4 * 4];
            }
        }

        const float* buf = sT + (tile & 1) * (128 * 64);
        const float* P   = (tile >> 2) ? sPq : sP;
        const float* Pr0 = P + jg * 8 * SP_STRIDE;

        float acc[8][2] = {};
        #pragma unroll 2
        for (int k = 0; k < 128; k += 4) {
            float pk[8][4];
            float tk[4][2];
            #pragma unroll
            for (int a = 0; a < 8; a++)
                *(float4*)pk[a] = *(const float4*)&Pr0[a * SP_STRIDE + k];
            #pragma unroll
            for (int kk = 0; kk < 4; kk++)
                *(float2*)tk[kk] = *(const float2*)&buf[(k + kk) * 64 + dg * 2];
            #pragma unroll
            for (int a = 0; a < 8; a++)
                #pragma unroll
                for (int kk = 0; kk < 4; kk++) {
                    acc[a][0] = fmaf(pk[a][kk], tk[kk][0], acc[a][0]);
                    acc[a][1] = fmaf(pk[a][kk], tk[kk][1], acc[a][1]);
                }
        }

        // Store prefetched tile into the other buffer.
        if (tile < 7) {
            float* bufN = sT + ((tile + 1) & 1) * (128 * 64);
            #pragma unroll
            for (int u = 0; u < 4; u++) {
                int idx = t + u * NT;
                int k = idx >> 4, c4 = idx & 15;
                *(float4*)&bufN[k * 64 + c4 * 4] = pf[u];
            }
        }

        int dglob = (tile >> 2) * 256 + (tile & 3) * 64 + dg * 2;
        #pragma unroll
        for (int a = 0; a < 8; a++) {
            int j = jg * 8 + a;
            float x = acc[a][0], y = acc[a][1];
            *(float2*)&outBase[(size_t)j * TWO_D + dglob] = make_float2(x, y);
            ls1[a] += x + y;
            ls2[a] = fmaf(x, x, fmaf(y, y, ls2[a]));
        }
        __syncthreads();
    }

    // ---- LN stats reduction (reuse sT as scratch; no atomics) ----
    {
        float* red1 = sT;                  // 128*33 floats
        float* red2 = sT + 128 * 33;       // 128*33 floats (total 8448 < 16384)
        #pragma unroll
        for (int a = 0; a < 8; a++) {
            int j = jg * 8 + a;
            red1[j * 33 + dg] = ls1[a];
            red2[j * 33 + dg] = ls2[a];
        }
        __syncthreads();
        if (t < 128) {
            float s1 = 0.f, s2 = 0.f;
            const float* r1 = red1 + t * 33;
            const float* r2 = red2 + t * 33;
            #pragma unroll
            for (int u = 0; u < 32; u++) { s1 += r1[u]; s2 += r2[u]; }
            float mu  = s1 * (1.0f / 512.0f);
            float var = s2 * (1.0f / 512.0f) - mu * mu;
            sMu[t] = mu;
            sRs[t] = rsqrtf(var + 1e-5f);
        }
        __syncthreads();
    }

    // ---- Phase C: LayerNorm in place (region is L2-hot) ----
    // 128 rows x 128 float4; 4 threads per row.
    int jr = t >> 2, part = t & 3;
    float mu = sMu[jr], rs = sRs[jr];
    float* orow = outBase + (size_t)jr * TWO_D;
    #pragma unroll 4
    for (int it = 0; it < 32; it++) {
        int idx4 = it * 4 + part;       // 0..127
        int d = idx4 * 4;
        float4 x = *(float4*)&orow[d];
        x.x = (x.x - mu) * rs * sW[d + 0] + sBi[d + 0];
        x.y = (x.y - mu) * rs * sW[d + 1] + sBi[d + 1];
        x.z = (x.z - mu) * rs * sW[d + 2] + sBi[d + 2];
        x.w = (x.w - mu) * rs * sW[d + 3] + sBi[d + 3];
        *(float4*)&orow[d] = x;
    }
}

// ---------------------------------------------------------------------------
extern "C" void kernel_launch(void* const* d_in, const int* in_sizes, int n_in,
                              void* d_out, int out_size)
{
    const float* q    = (const float*)d_in[0];
    const float* v    = (const float*)d_in[1];
    const int*   mask = (const int*)d_in[2];
    const float* nw   = (const float*)d_in[3];
    const float* nb   = (const float*)d_in[4];
    float* out = (float*)d_out;

    compact_kernel<<<1, BB * LL>>>(mask);
    gram_kernel<<<dim3(16, BB), 256>>>(q, v, mask);

    cudaFuncSetAttribute(attn_kernel,
                         cudaFuncAttributeMaxDynamicSharedMemorySize, SMEM_BYTES);
    attn_kernel<<<BB * LL, NT, SMEM_BYTES>>>(q, v, nw, nb, out);
}

// round 10
// speedup vs baseline: 2.1202x; 1.5569x over previous
#include <cuda_runtime.h>
#include <cuda_bf16.h>
#include <cstdint>

#define BB 4
#define LL 128
#define DD 256
#define TWO_D 512

// Gram scratch: [b][type][r][k], types: 0=0.5*Q.V^T(+mask), 1=0.5*V.V^T,
//                                        2=0.5*Q.Q^T(+mask), 3=0.5*V.Q^T
__device__ float g_gram[BB * 4 * LL * LL];

// Mask compaction lists: pair = b*128 + i
__device__ int g_active[BB * LL];
__device__ int g_inactive[BB * LL];
__device__ int g_nactive;

// ---------------------------------------------------------------------------
// Kernel 0: compact mask into active/inactive pair lists. 1 block, 512 thr.
// ---------------------------------------------------------------------------
__global__ __launch_bounds__(BB * LL) void compact_kernel(
    const int* __restrict__ mask)
{
    __shared__ int cA, cI;
    int t = threadIdx.x;
    if (t == 0) { cA = 0; cI = 0; }
    __syncthreads();
    if (mask[t]) { int p = atomicAdd(&cA, 1); g_active[p] = t; }
    else         { int p = atomicAdd(&cI, 1); g_inactive[p] = t; }
    __syncthreads();
    if (t == 0) g_nactive = cA;
}

// ---------------------------------------------------------------------------
// Kernel 1: Gram matrices. grid (16, B). 256 threads.
// ---------------------------------------------------------------------------
__global__ __launch_bounds__(256) void gram_kernel(
    const float* __restrict__ Q, const float* __restrict__ V,
    const int* __restrict__ mask)
{
    int b    = blockIdx.y;
    int type = blockIdx.x >> 2;
    int rq   = blockIdx.x & 3;
    const float* A  = ((type & 1) ? V : Q) + (size_t)b * LL * DD;
    const float* Bm = ((type < 2) ? V : Q) + (size_t)b * LL * DD;
    int r0 = rq * 32;

    __shared__ float sA[32 * 65];
    __shared__ float sB[128 * 65];

    float acc[4][4] = {};
    int t = threadIdx.x;

    for (int dc = 0; dc < DD; dc += 64) {
        #pragma unroll
        for (int u = 0; u < 32; u++) {
            int idx = t + u * 256;
            int r = idx >> 6, d = idx & 63;
            sB[r * 65 + d] = Bm[r * DD + dc + d];
        }
        #pragma unroll
        for (int u = 0; u < 8; u++) {
            int idx = t + u * 256;
            int r = idx >> 6, d = idx & 63;
            sA[r * 65 + d] = A[(r0 + r) * DD + dc + d];
        }
        __syncthreads();

        int rg = t >> 5, kg = t & 31;
        const float* sAr = sA + rg * 4 * 65;
        const float* sBr = sB + kg * 4 * 65;
        #pragma unroll 8
        for (int d = 0; d < 64; d++) {
            float av[4], bv[4];
            #pragma unroll
            for (int a = 0; a < 4; a++) av[a] = sAr[a * 65 + d];
            #pragma unroll
            for (int c = 0; c < 4; c++) bv[c] = sBr[c * 65 + d];
            #pragma unroll
            for (int a = 0; a < 4; a++)
                #pragma unroll
                for (int c = 0; c < 4; c++)
                    acc[a][c] = fmaf(av[a], bv[c], acc[a][c]);
        }
        __syncthreads();
    }

    int rg = t >> 5, kg = t & 31;
    float* G = g_gram + (size_t)(b * 4 + type) * LL * LL;
    bool doMask = (type == 0) || (type == 2);
    #pragma unroll
    for (int a = 0; a < 4; a++) {
        #pragma unroll
        for (int c = 0; c < 4; c++) {
            int k = kg * 4 + c;
            float val = 0.5f * acc[a][c];
            if (doMask && mask[b * LL + k] == 0) val = -1e30f;
            G[(r0 + rg * 4 + a) * LL + k] = val;
        }
    }
}

// ---------------------------------------------------------------------------
// mma.sync bf16 helper (m16n8k16, row.col, fp32 accumulate)
// ---------------------------------------------------------------------------
__device__ __forceinline__ void mma_bf16(float* c, const uint32_t* a,
                                         uint32_t b0, uint32_t b1)
{
    asm volatile(
        "mma.sync.aligned.m16n8k16.row.col.f32.bf16.bf16.f32 "
        "{%0,%1,%2,%3}, {%4,%5,%6,%7}, {%8,%9}, {%0,%1,%2,%3};"
        : "+f"(c[0]), "+f"(c[1]), "+f"(c[2]), "+f"(c[3])
        : "r"(a[0]), "r"(a[1]), "r"(a[2]), "r"(a[3]), "r"(b0), "r"(b1));
}

// ---------------------------------------------------------------------------
// Kernel 2: attention via mma.sync bf16x3 + LayerNorm.
// One block per (b,i), 512 threads.
// Layouts: P planes [128 j][136 k] bf16 (hi/lo). Vt planes [64 d][136 k] bf16.
// Stride 136 bf16 = 68 b32 (== 4 mod 32) -> conflict-free fragment loads.
// ---------------------------------------------------------------------------
#define NT 512
#define PSTR 136                       // bf16 elements per row
// byte offsets in dynamic smem
#define OB_PHI   0                     // 128*136*2 = 34816
#define OB_PLO   34816                 // 34816
#define OB_VHI   69632                 // 64*136*2 = 17408
#define OB_VLO   87040                 // 17408
#define OB_G1    104448                // 128 f
#define OB_G1Q   104960                // 128 f
#define OB_W     105472                // 512 f
#define OB_BI    107520                // 512 f
#define OB_ST1   109568                // 128*4 f
#define OB_ST2   111616                // 128*4 f
#define OB_MU    113664                // 128 f
#define OB_RS    114176                // 128 f
#define SMEM_BYTES 114688

__global__ __launch_bounds__(NT, 1) void attn_kernel(
    const float* __restrict__ Q, const float* __restrict__ V,
    const float* __restrict__ nw, const float* __restrict__ nb,
    float* __restrict__ out)
{
    int bid = blockIdx.x;
    int t   = threadIdx.x;
    int nA  = g_nactive;
    bool active = (bid < nA);
    int pair = active ? g_active[bid] : g_inactive[bid - nA];
    int b = pair >> 7, i = pair & 127;
    float* outBase = out + ((size_t)(b * LL + i)) * LL * TWO_D; // [128 j][512 d]

    if (!active) {
        float4 z = make_float4(0.f, 0.f, 0.f, 0.f);
        float4* o4 = (float4*)outBase;
        #pragma unroll
        for (int u = 0; u < 32; u++) o4[t + u * NT] = z;
        return;
    }

    extern __shared__ char smc[];
    __nv_bfloat16* sPhi = (__nv_bfloat16*)(smc + OB_PHI);
    __nv_bfloat16* sPlo = (__nv_bfloat16*)(smc + OB_PLO);
    __nv_bfloat16* sVhi = (__nv_bfloat16*)(smc + OB_VHI);
    __nv_bfloat16* sVlo = (__nv_bfloat16*)(smc + OB_VLO);
    const uint32_t* PH = (const uint32_t*)(smc + OB_PHI);
    const uint32_t* PL = (const uint32_t*)(smc + OB_PLO);
    const uint32_t* VH = (const uint32_t*)(smc + OB_VHI);
    const uint32_t* VL = (const uint32_t*)(smc + OB_VLO);
    float* sG1  = (float*)(smc + OB_G1);
    float* sG1q = (float*)(smc + OB_G1Q);
    float* sW   = (float*)(smc + OB_W);
    float* sBi  = (float*)(smc + OB_BI);
    float* sST1 = (float*)(smc + OB_ST1);
    float* sST2 = (float*)(smc + OB_ST2);
    float* sMu  = (float*)(smc + OB_MU);
    float* sRs  = (float*)(smc + OB_RS);

    const float* G   = g_gram + (size_t)b * 4 * LL * LL;
    const float* G2  = G + 1 * LL * LL;   // 0.5*V.V^T
    const float* G2q = G + 3 * LL * LL;   // 0.5*V.Q^T
    const float* QB = Q + (size_t)b * LL * DD;
    const float* VB = V + (size_t)b * LL * DD;

    int warp = t >> 5, lane = t & 31;
    int g  = lane >> 2;      // 0..7
    int tq = lane & 3;       // 0..3
    int mbase = (warp >> 2) * 32;   // j tile base (4 m-tiles)
    int nsub  = warp & 3;           // d sub-tile (16 d each within 64-d tile)
    int nbase = nsub * 16;

    if (t < 128) {
        sG1[t]  = G[i * LL + t];                 // masked 0.5*q_i . v_k
        sG1q[t] = G[2 * LL * LL + i * LL + t];   // masked 0.5*q_i . q_k
    }
    sW[t]  = nw[t];
    sBi[t] = nb[t];

    // Prefetch V tile (it=0: side 0, dbase 0) into registers.
    float pf[16];
    #pragma unroll
    for (int u = 0; u < 16; u++) {
        int idx = t + u * NT;            // 0..8191
        int k = idx >> 6, ds = idx & 63;
        pf[u] = VB[k * DD + ds];
    }
    __syncthreads();

    float ls1[4] = {}, ls2[4] = {};

    #pragma unroll 1
    for (int it = 0; it < 8; it++) {
        int s  = it >> 2;
        int dt = it & 3;

        if (dt == 0) {
            // softmax for side s -> P hi/lo planes (needs prev compute done)
            if (it > 0) __syncthreads();
            const float* Grow = s ? G2q : G2;
            const float* g1   = s ? sG1q : sG1;
            for (int jj = warp; jj < 128; jj += 16) {
                const float* r = Grow + jj * LL;
                float s0 = g1[lane]      + r[lane];
                float s1 = g1[lane + 32] + r[lane + 32];
                float s2 = g1[lane + 64] + r[lane + 64];
                float s3 = g1[lane + 96] + r[lane + 96];
                float m = fmaxf(fmaxf(s0, s1), fmaxf(s2, s3));
                #pragma unroll
                for (int o = 16; o; o >>= 1) m = fmaxf(m, __shfl_xor_sync(0xffffffffu, m, o));
                float e0 = __expf(s0 - m), e1 = __expf(s1 - m);
                float e2 = __expf(s2 - m), e3 = __expf(s3 - m);
                float su = e0 + e1 + e2 + e3;
                #pragma unroll
                for (int o = 16; o; o >>= 1) su += __shfl_xor_sync(0xffffffffu, su, o);
                float inv = 1.0f / su;
                float vals[4] = {e0 * inv, e1 * inv, e2 * inv, e3 * inv};
                #pragma unroll
                for (int c = 0; c < 4; c++) {
                    int k = lane + c * 32;
                    float x = vals[c];
                    __nv_bfloat16 h = __float2bfloat16(x);
                    __nv_bfloat16 l = __float2bfloat16(x - __bfloat162float(h));
                    sPhi[jj * PSTR + k] = h;
                    sPlo[jj * PSTR + k] = l;
                }
            }
        } else {
            __syncthreads();  // prev compute done before Vt overwrite
        }

        // Store prefetched tile -> Vt planes (transposed, bf16 split).
        #pragma unroll
        for (int u = 0; u < 16; u++) {
            int idx = t + u * NT;
            int k = idx >> 6, ds = idx & 63;
            float x = pf[u];
            __nv_bfloat16 h = __float2bfloat16(x);
            __nv_bfloat16 l = __float2bfloat16(x - __bfloat162float(h));
            sVhi[ds * PSTR + k] = h;
            sVlo[ds * PSTR + k] = l;
        }
        __syncthreads();

        // Prefetch next tile.
        if (it < 7) {
            int nx = it + 1;
            const float* src = (nx >> 2) ? QB : VB;
            int dbase = (nx & 3) * 64;
            #pragma unroll
            for (int u = 0; u < 16; u++) {
                int idx = t + u * NT;
                int k = idx >> 6, ds = idx & 63;
                pf[u] = src[k * DD + dbase + ds];
            }
        }

        // ---- MMA compute: warp tile 32j x 16d, k = 128 ----
        float acc[2][2][4] = {};
        #pragma unroll
        for (int ks = 0; ks < 8; ks++) {
            int kb = ks * 8 + tq;
            uint32_t ah[2][4], al[2][4], bh[2][2], bl[2][2];
            #pragma unroll
            for (int mt = 0; mt < 2; mt++) {
                int r = (mbase + mt * 16 + g) * 68 + kb;
                ah[mt][0] = PH[r];          ah[mt][1] = PH[r + 8 * 68];
                ah[mt][2] = PH[r + 4];      ah[mt][3] = PH[r + 8 * 68 + 4];
                al[mt][0] = PL[r];          al[mt][1] = PL[r + 8 * 68];
                al[mt][2] = PL[r + 4];      al[mt][3] = PL[r + 8 * 68 + 4];
            }
            #pragma unroll
            for (int nt = 0; nt < 2; nt++) {
                int r = (nbase + nt * 8 + g) * 68 + kb;
                bh[nt][0] = VH[r];  bh[nt][1] = VH[r + 4];
                bl[nt][0] = VL[r];  bl[nt][1] = VL[r + 4];
            }
            #pragma unroll
            for (int mt = 0; mt < 2; mt++)
                #pragma unroll
                for (int nt = 0; nt < 2; nt++) {
                    mma_bf16(acc[mt][nt], ah[mt], bh[nt][0], bh[nt][1]);
                    mma_bf16(acc[mt][nt], ah[mt], bl[nt][0], bl[nt][1]);
                    mma_bf16(acc[mt][nt], al[mt], bh[nt][0], bh[nt][1]);
                }
        }

        // Store raw output + accumulate LN stats.
        int colb = s * 256 + dt * 64 + nbase;
        #pragma unroll
        for (int mt = 0; mt < 2; mt++)
            #pragma unroll
            for (int nt = 0; nt < 2; nt++) {
                const float* a4 = acc[mt][nt];
                int r0 = mbase + mt * 16 + g;
                int c0 = colb + nt * 8 + tq * 2;
                *(float2*)&outBase[(size_t)r0 * TWO_D + c0] =
                    make_float2(a4[0], a4[1]);
                *(float2*)&outBase[(size_t)(r0 + 8) * TWO_D + c0] =
                    make_float2(a4[2], a4[3]);
                ls1[mt * 2 + 0] += a4[0] + a4[1];
                ls2[mt * 2 + 0] = fmaf(a4[0], a4[0], fmaf(a4[1], a4[1], ls2[mt * 2 + 0]));
                ls1[mt * 2 + 1] += a4[2] + a4[3];
                ls2[mt * 2 + 1] = fmaf(a4[2], a4[2], fmaf(a4[3], a4[3], ls2[mt * 2 + 1]));
            }
    }

    // ---- LN stats: shfl-reduce across quad lanes, then smem reduce ----
    #pragma unroll
    for (int ss = 0; ss < 4; ss++) {
        float v1 = ls1[ss], v2 = ls2[ss];
        v1 += __shfl_xor_sync(0xffffffffu, v1, 1);
        v1 += __shfl_xor_sync(0xffffffffu, v1, 2);
        v2 += __shfl_xor_sync(0xffffffffu, v2, 1);
        v2 += __shfl_xor_sync(0xffffffffu, v2, 2);
        if (tq == 0) {
            int row = mbase + ss * 8 + g;
            sST1[row * 4 + nsub] = v1;
            sST2[row * 4 + nsub] = v2;
        }
    }
    __syncthreads();
    if (t < 128) {
        float a1 = sST1[t * 4 + 0] + sST1[t * 4 + 1] + sST1[t * 4 + 2] + sST1[t * 4 + 3];
        float a2 = sST2[t * 4 + 0] + sST2[t * 4 + 1] + sST2[t * 4 + 2] + sST2[t * 4 + 3];
        float mu  = a1 * (1.0f / 512.0f);
        float var = a2 * (1.0f / 512.0f) - mu * mu;
        sMu[t] = mu;
        sRs[t] = rsqrtf(var + 1e-5f);
    }
    __syncthreads();

    // ---- Phase C: LayerNorm in place (region is L2-hot) ----
    int jr = t >> 2, part = t & 3;
    float mu = sMu[jr], rs = sRs[jr];
    float* orow = outBase + (size_t)jr * TWO_D;
    #pragma unroll 4
    for (int itc = 0; itc < 32; itc++) {
        int idx4 = itc * 4 + part;       // 0..127
        int d = idx4 * 4;
        float4 x = *(float4*)&orow[d];
        x.x = (x.x - mu) * rs * sW[d + 0] + sBi[d + 0];
        x.y = (x.y - mu) * rs * sW[d + 1] + sBi[d + 1];
        x.z = (x.z - mu) * rs * sW[d + 2] + sBi[d + 2];
        x.w = (x.w - mu) * rs * sW[d + 3] + sBi[d + 3];
        *(float4*)&orow[d] = x;
    }
}

// ---------------------------------------------------------------------------
extern "C" void kernel_launch(void* const* d_in, const int* in_sizes, int n_in,
                              void* d_out, int out_size)
{
    const float* q    = (const float*)d_in[0];
    const float* v    = (const float*)d_in[1];
    const int*   mask = (const int*)d_in[2];
    const float* nw   = (const float*)d_in[3];
    const float* nb   = (const float*)d_in[4];
    float* out = (float*)d_out;

    compact_kernel<<<1, BB * LL>>>(mask);
    gram_kernel<<<dim3(16, BB), 256>>>(q, v, mask);

    cudaFuncSetAttribute(attn_kernel,
                         cudaFuncAttributeMaxDynamicSharedMemorySize, SMEM_BYTES);
    attn_kernel<<<BB * LL, NT, SMEM_BYTES>>>(q, v, nw, nb, out);
}

// round 11
// speedup vs baseline: 2.5000x; 1.1792x over previous
#include <cuda_runtime.h>
#include <cuda_bf16.h>
#include <cstdint>

#define BB 4
#define LL 128
#define DD 256
#define TWO_D 512

// Gram scratch: [b][type][r][k], types: 0=0.5*Q.V^T(+mask), 1=0.5*V.V^T,
//                                        2=0.5*Q.Q^T(+mask), 3=0.5*V.Q^T
__device__ float g_gram[BB * 4 * LL * LL];

// Mask compaction lists: pair = b*128 + i
__device__ int g_active[BB * LL];
__device__ int g_inactive[BB * LL];
__device__ int g_nactive;

// ---------------------------------------------------------------------------
// Kernel 1: Gram matrices. grid (16, B). 256 threads.
// Block (0,0) additionally compacts the mask into active/inactive lists.
// ---------------------------------------------------------------------------
__global__ __launch_bounds__(256) void gram_kernel(
    const float* __restrict__ Q, const float* __restrict__ V,
    const int* __restrict__ mask)
{
    int t = threadIdx.x;

    if (blockIdx.x == 0 && blockIdx.y == 0) {
        __shared__ int cA, cI;
        if (t == 0) { cA = 0; cI = 0; }
        __syncthreads();
        for (int e = t; e < BB * LL; e += 256) {
            if (mask[e]) g_active[atomicAdd(&cA, 1)] = e;
            else         g_inactive[atomicAdd(&cI, 1)] = e;
        }
        __syncthreads();
        if (t == 0) g_nactive = cA;
    }

    int b    = blockIdx.y;
    int type = blockIdx.x >> 2;
    int rq   = blockIdx.x & 3;
    const float* A  = ((type & 1) ? V : Q) + (size_t)b * LL * DD;
    const float* Bm = ((type < 2) ? V : Q) + (size_t)b * LL * DD;
    int r0 = rq * 32;

    __shared__ float sA[32 * 65];
    __shared__ float sB[128 * 65];

    float acc[4][4] = {};

    for (int dc = 0; dc < DD; dc += 64) {
        #pragma unroll
        for (int u = 0; u < 32; u++) {
            int idx = t + u * 256;
            int r = idx >> 6, d = idx & 63;
            sB[r * 65 + d] = Bm[r * DD + dc + d];
        }
        #pragma unroll
        for (int u = 0; u < 8; u++) {
            int idx = t + u * 256;
            int r = idx >> 6, d = idx & 63;
            sA[r * 65 + d] = A[(r0 + r) * DD + dc + d];
        }
        __syncthreads();

        int rg = t >> 5, kg = t & 31;
        const float* sAr = sA + rg * 4 * 65;
        const float* sBr = sB + kg * 4 * 65;
        #pragma unroll 8
        for (int d = 0; d < 64; d++) {
            float av[4], bv[4];
            #pragma unroll
            for (int a = 0; a < 4; a++) av[a] = sAr[a * 65 + d];
            #pragma unroll
            for (int c = 0; c < 4; c++) bv[c] = sBr[c * 65 + d];
            #pragma unroll
            for (int a = 0; a < 4; a++)
                #pragma unroll
                for (int c = 0; c < 4; c++)
                    acc[a][c] = fmaf(av[a], bv[c], acc[a][c]);
        }
        __syncthreads();
    }

    int rg = t >> 5, kg = t & 31;
    float* G = g_gram + (size_t)(b * 4 + type) * LL * LL;
    bool doMask = (type == 0) || (type == 2);
    #pragma unroll
    for (int a = 0; a < 4; a++) {
        #pragma unroll
        for (int c = 0; c < 4; c++) {
            int k = kg * 4 + c;
            float val = 0.5f * acc[a][c];
            if (doMask && mask[b * LL + k] == 0) val = -1e30f;
            G[(r0 + rg * 4 + a) * LL + k] = val;
        }
    }
}

// ---------------------------------------------------------------------------
// mma.sync / ldmatrix helpers
// ---------------------------------------------------------------------------
__device__ __forceinline__ void mma_bf16(float* c, const uint32_t* a,
                                         uint32_t b0, uint32_t b1)
{
    asm volatile(
        "mma.sync.aligned.m16n8k16.row.col.f32.bf16.bf16.f32 "
        "{%0,%1,%2,%3}, {%4,%5,%6,%7}, {%8,%9}, {%0,%1,%2,%3};"
        : "+f"(c[0]), "+f"(c[1]), "+f"(c[2]), "+f"(c[3])
        : "r"(a[0]), "r"(a[1]), "r"(a[2]), "r"(a[3]), "r"(b0), "r"(b1));
}
__device__ __forceinline__ void ldsm_x4(uint32_t* r, uint32_t addr)
{
    asm volatile("ldmatrix.sync.aligned.m8n8.x4.shared.b16 {%0,%1,%2,%3}, [%4];"
        : "=r"(r[0]), "=r"(r[1]), "=r"(r[2]), "=r"(r[3]) : "r"(addr));
}
__device__ __forceinline__ void ldsm_x4_t(uint32_t* r, uint32_t addr)
{
    asm volatile("ldmatrix.sync.aligned.m8n8.x4.trans.shared.b16 {%0,%1,%2,%3}, [%4];"
        : "=r"(r[0]), "=r"(r[1]), "=r"(r[2]), "=r"(r[3]) : "r"(addr));
}

// ---------------------------------------------------------------------------
// Kernel 2: attention via mma.sync bf16x3 (ldmatrix fragments) + LayerNorm.
// One block per (b,i), 512 threads.
// P planes   [128 j][136 k] bf16 (hi/lo)      row stride 272B (!≡0 mod 128)
// V planes   [128 k][72  d] bf16, K-MAJOR     row stride 144B (!≡0 mod 128)
//            2 buffers x (hi, lo), transpose done by ldmatrix.x4.trans.
// ---------------------------------------------------------------------------
#define NT 512
#define PSTR 136
#define VSTR 72
// byte offsets in dynamic smem
#define OB_PHI   0                     // 128*136*2 = 34816
#define OB_PLO   34816                 // 34816
#define OB_V     69632                 // 4 x 18432 = 73728  [buf][plane]
#define VPL      18432                 // bytes per V plane
#define OB_G1    143360                // 128 f
#define OB_G1Q   143872                // 128 f
#define OB_W     144384                // 512 f
#define OB_BI    146432                // 512 f
#define OB_ST1   148480                // 128*4 f
#define OB_ST2   150528                // 128*4 f
#define OB_MU    152576                // 128 f
#define OB_RS    153088                // 128 f
#define SMEM_BYTES 153600

__global__ __launch_bounds__(NT, 1) void attn_kernel(
    const float* __restrict__ Q, const float* __restrict__ V,
    const float* __restrict__ nw, const float* __restrict__ nb,
    float* __restrict__ out)
{
    int bid = blockIdx.x;
    int t   = threadIdx.x;
    int nA  = g_nactive;
    bool active = (bid < nA);
    int pair = active ? g_active[bid] : g_inactive[bid - nA];
    int b = pair >> 7, i = pair & 127;
    float* outBase = out + ((size_t)(b * LL + i)) * LL * TWO_D; // [128 j][512 d]

    if (!active) {
        float4 z = make_float4(0.f, 0.f, 0.f, 0.f);
        float4* o4 = (float4*)outBase;
        #pragma unroll
        for (int u = 0; u < 32; u++) o4[t + u * NT] = z;
        return;
    }

    extern __shared__ char smc[];
    uint32_t smb = (uint32_t)__cvta_generic_to_shared(smc);

    __nv_bfloat16* sPhi = (__nv_bfloat16*)(smc + OB_PHI);
    __nv_bfloat16* sPlo = (__nv_bfloat16*)(smc + OB_PLO);
    float* sG1  = (float*)(smc + OB_G1);
    float* sG1q = (float*)(smc + OB_G1Q);
    float* sW   = (float*)(smc + OB_W);
    float* sBi  = (float*)(smc + OB_BI);
    float* sST1 = (float*)(smc + OB_ST1);
    float* sST2 = (float*)(smc + OB_ST2);
    float* sMu  = (float*)(smc + OB_MU);
    float* sRs  = (float*)(smc + OB_RS);

    const float* G   = g_gram + (size_t)b * 4 * LL * LL;
    const float* G2  = G + 1 * LL * LL;   // 0.5*V.V^T
    const float* G2q = G + 3 * LL * LL;   // 0.5*V.Q^T
    const float* QB = Q + (size_t)b * LL * DD;
    const float* VB = V + (size_t)b * LL * DD;

    int warp = t >> 5, lane = t & 31;
    int g  = lane >> 2;      // 0..7
    int tq = lane & 3;       // 0..3
    int mbase = (warp >> 2) * 32;   // j tile base
    int nsub  = warp & 3;           // 16-d sub-tile within the 64-d tile
    int nbase = nsub * 16;

    // ldmatrix lane addressing (mat = lane>>3, r = lane&7)
    int mat = lane >> 3, mr = lane & 7;
    // A: row = mbase + (mat&1)*8 + mr, kofs = (mat>>1)*8   (mt1: +16 rows)
    uint32_t aAddrH = smb + OB_PHI +
        (uint32_t)(((mbase + (mat & 1) * 8 + mr) * PSTR + (mat >> 1) * 8) * 2);
    uint32_t aAddrL = aAddrH + (OB_PLO - OB_PHI);
    // B: k = (mat&1)*8 + mr (+16 per ktile), n = nbase + (mat>>1)*8
    uint32_t bAddr0 = smb + OB_V +
        (uint32_t)((((mat & 1) * 8 + mr) * VSTR + nbase + (mat >> 1) * 8) * 2);

    if (t < 128) {
        sG1[t]  = G[i * LL + t];                 // masked 0.5*q_i . v_k
        sG1q[t] = G[2 * LL * LL + i * LL + t];   // masked 0.5*q_i . q_k
    }
    sW[t]  = nw[t];
    sBi[t] = nb[t];

    // Prefetch V tile 0 (side 0, dbase 0) as float2 (lane -> d pairs).
    float2 pf[8];
    #pragma unroll
    for (int u = 0; u < 8; u++) {
        int idx = t + u * NT;            // 0..4095 (float2 slots)
        int k = idx >> 5, dp = idx & 31;
        pf[u] = *(const float2*)&VB[k * DD + dp * 2];
    }

    // ---- softmax side 0 -> P planes ----
    {
        const float* Grow = G2;
        const float* g1v  = G + i * LL;   // sG1 not yet visible; use gmem? No:
        (void)g1v;
    }
    __syncthreads();   // sG1/sG1q visible

    auto softmax_side = [&](const float* Grow, const float* g1) {
        for (int jj = warp; jj < 128; jj += 16) {
            const float* r = Grow + jj * LL;
            float s0 = g1[lane]      + r[lane];
            float s1 = g1[lane + 32] + r[lane + 32];
            float s2 = g1[lane + 64] + r[lane + 64];
            float s3 = g1[lane + 96] + r[lane + 96];
            float m = fmaxf(fmaxf(s0, s1), fmaxf(s2, s3));
            #pragma unroll
            for (int o = 16; o; o >>= 1) m = fmaxf(m, __shfl_xor_sync(0xffffffffu, m, o));
            float e0 = __expf(s0 - m), e1 = __expf(s1 - m);
            float e2 = __expf(s2 - m), e3 = __expf(s3 - m);
            float su = e0 + e1 + e2 + e3;
            #pragma unroll
            for (int o = 16; o; o >>= 1) su += __shfl_xor_sync(0xffffffffu, su, o);
            float inv = 1.0f / su;
            float vals[4] = {e0 * inv, e1 * inv, e2 * inv, e3 * inv};
            #pragma unroll
            for (int c = 0; c < 4; c++) {
                int k = lane + c * 32;
                float x = vals[c];
                __nv_bfloat16 h = __float2bfloat16(x);
                __nv_bfloat16 l = __float2bfloat16(x - __bfloat162float(h));
                sPhi[jj * PSTR + k] = h;
                sPlo[jj * PSTR + k] = l;
            }
        }
    };
    softmax_side(G2, sG1);

    // Store tile 0 -> V buffer 0 (K-major, bf16x2 packed, conflict-free).
    auto store_vtile = [&](int buf, const float2* src) {
        uint32_t* vhi = (uint32_t*)(smc + OB_V + buf * 2 * VPL);
        uint32_t* vlo = (uint32_t*)(smc + OB_V + buf * 2 * VPL + VPL);
        #pragma unroll
        for (int u = 0; u < 8; u++) {
            int idx = t + u * NT;
            int k = idx >> 5, dp = idx & 31;
            float x = src[u].x, y = src[u].y;
            __nv_bfloat162 h2 = __floats2bfloat162_rn(x, y);
            float rx = x - __bfloat162float(h2.x);
            float ry = y - __bfloat162float(h2.y);
            __nv_bfloat162 l2 = __floats2bfloat162_rn(rx, ry);
            int w = k * (VSTR / 2) + dp;   // 32-bit word index (VSTR even)
            vhi[w] = *(uint32_t*)&h2;
            vlo[w] = *(uint32_t*)&l2;
        }
    };
    store_vtile(0, pf);
    __syncthreads();

    float ls1[4] = {}, ls2[4] = {};

    #pragma unroll 1
    for (int it = 0; it < 8; it++) {
        int s   = it >> 2;
        int dt  = it & 3;
        int buf = it & 1;

        // Prefetch next tile (gmem loads in flight during MMA).
        if (it < 7) {
            int nx = it + 1;
            const float* src = (nx >> 2) ? QB : VB;
            int dbase = (nx & 3) * 64;
            #pragma unroll
            for (int u = 0; u < 8; u++) {
                int idx = t + u * NT;
                int k = idx >> 5, dp = idx & 31;
                pf[u] = *(const float2*)&src[k * DD + dbase + dp * 2];
            }
        }

        // ---- MMA compute: warp tile 32j x 16d, k = 128 ----
        uint32_t bBase = bAddr0 + (uint32_t)(buf * 2 * VPL);
        float acc[2][2][4] = {};
        #pragma unroll
        for (int kt = 0; kt < 8; kt++) {
            uint32_t ah0[4], ah1[4], al0[4], al1[4], bh[4], bl[4];
            uint32_t ka = (uint32_t)(kt * 32);       // 16 bf16 = 32B
            uint32_t kb = (uint32_t)(kt * 16 * VSTR * 2);
            ldsm_x4(ah0, aAddrH + ka);
            ldsm_x4(ah1, aAddrH + 16 * PSTR * 2 + ka);
            ldsm_x4(al0, aAddrL + ka);
            ldsm_x4(al1, aAddrL + 16 * PSTR * 2 + ka);
            ldsm_x4_t(bh, bBase + kb);
            ldsm_x4_t(bl, bBase + VPL + kb);
            // hi*hi
            mma_bf16(acc[0][0], ah0, bh[0], bh[1]);
            mma_bf16(acc[0][1], ah0, bh[2], bh[3]);
            mma_bf16(acc[1][0], ah1, bh[0], bh[1]);
            mma_bf16(acc[1][1], ah1, bh[2], bh[3]);
            // hi*lo
            mma_bf16(acc[0][0], ah0, bl[0], bl[1]);
            mma_bf16(acc[0][1], ah0, bl[2], bl[3]);
            mma_bf16(acc[1][0], ah1, bl[0], bl[1]);
            mma_bf16(acc[1][1], ah1, bl[2], bl[3]);
            // lo*hi
            mma_bf16(acc[0][0], al0, bh[0], bh[1]);
            mma_bf16(acc[0][1], al0, bh[2], bh[3]);
            mma_bf16(acc[1][0], al1, bh[0], bh[1]);
            mma_bf16(acc[1][1], al1, bh[2], bh[3]);
        }

        // Store raw output + accumulate LN stats.
        int colb = s * 256 + dt * 64 + nbase;
        #pragma unroll
        for (int mt = 0; mt < 2; mt++)
            #pragma unroll
            for (int nt = 0; nt < 2; nt++) {
                const float* a4 = acc[mt][nt];
                int r0 = mbase + mt * 16 + g;
                int c0 = colb + nt * 8 + tq * 2;
                *(float2*)&outBase[(size_t)r0 * TWO_D + c0] =
                    make_float2(a4[0], a4[1]);
                *(float2*)&outBase[(size_t)(r0 + 8) * TWO_D + c0] =
                    make_float2(a4[2], a4[3]);
                ls1[mt * 2 + 0] += a4[0] + a4[1];
                ls2[mt * 2 + 0] = fmaf(a4[0], a4[0], fmaf(a4[1], a4[1], ls2[mt * 2 + 0]));
                ls1[mt * 2 + 1] += a4[2] + a4[3];
                ls2[mt * 2 + 1] = fmaf(a4[2], a4[2], fmaf(a4[3], a4[3], ls2[mt * 2 + 1]));
            }

        if (it == 3) {
            __syncthreads();            // all P reads done
            softmax_side(G2q, sG1q);    // rewrite P planes for side 1
        }
        if (it < 7) {
            store_vtile((it + 1) & 1, pf);
            __syncthreads();
        }
    }

    // ---- LN stats: shfl-reduce across quad lanes, then smem reduce ----
    #pragma unroll
    for (int ss = 0; ss < 4; ss++) {
        float v1 = ls1[ss], v2 = ls2[ss];
        v1 += __shfl_xor_sync(0xffffffffu, v1, 1);
        v1 += __shfl_xor_sync(0xffffffffu, v1, 2);
        v2 += __shfl_xor_sync(0xffffffffu, v2, 1);
        v2 += __shfl_xor_sync(0xffffffffu, v2, 2);
        if (tq == 0) {
            int row = mbase + (ss >> 1) * 16 + (ss & 1) * 8 + g;
            sST1[row * 4 + nsub] = v1;
            sST2[row * 4 + nsub] = v2;
        }
    }
    __syncthreads();
    if (t < 128) {
        float a1 = sST1[t * 4 + 0] + sST1[t * 4 + 1] + sST1[t * 4 + 2] + sST1[t * 4 + 3];
        float a2 = sST2[t * 4 + 0] + sST2[t * 4 + 1] + sST2[t * 4 + 2] + sST2[t * 4 + 3];
        float mu  = a1 * (1.0f / 512.0f);
        float var = a2 * (1.0f / 512.0f) - mu * mu;
        sMu[t] = mu;
        sRs[t] = rsqrtf(var + 1e-5f);
    }
    __syncthreads();

    // ---- Phase C: LayerNorm in place (region is L2-hot) ----
    int jr = t >> 2, part = t & 3;
    float mu = sMu[jr], rs = sRs[jr];
    float* orow = outBase + (size_t)jr * TWO_D;
    #pragma unroll 4
    for (int itc = 0; itc < 32; itc++) {
        int idx4 = itc * 4 + part;       // 0..127
        int d = idx4 * 4;
        float4 x = *(float4*)&orow[d];
        x.x = (x.x - mu) * rs * sW[d + 0] + sBi[d + 0];
        x.y = (x.y - mu) * rs * sW[d + 1] + sBi[d + 1];
        x.z = (x.z - mu) * rs * sW[d + 2] + sBi[d + 2];
        x.w = (x.w - mu) * rs * sW[d + 3] + sBi[d + 3];
        *(float4*)&orow[d] = x;
    }
}

// ---------------------------------------------------------------------------
extern "C" void kernel_launch(void* const* d_in, const int* in_sizes, int n_in,
                              void* d_out, int out_size)
{
    const float* q    = (const float*)d_in[0];
    const float* v    = (const float*)d_in[1];
    const int*   mask = (const int*)d_in[2];
    const float* nw   = (const float*)d_in[3];
    const float* nb   = (const float*)d_in[4];
    float* out = (float*)d_out;

    gram_kernel<<<dim3(16, BB), 256>>>(q, v, mask);

    cudaFuncSetAttribute(attn_kernel,
                         cudaFuncAttributeMaxDynamicSharedMemorySize, SMEM_BYTES);
    attn_kernel<<<BB * LL, NT, SMEM_BYTES>>>(q, v, nw, nb, out);
}

// round 12
// speedup vs baseline: 2.6577x; 1.0631x over previous
#include <cuda_runtime.h>
#include <cuda_bf16.h>
#include <cstdint>

#define BB 4
#define LL 128
#define DD 256
#define TWO_D 512

// Gram scratch: [b][type][r][k], types: 0=0.5*Q.V^T(+mask), 1=0.5*V.V^T,
//                                        2=0.5*Q.Q^T(+mask), 3=0.5*V.Q^T
__device__ float g_gram[BB * 4 * LL * LL];

// Mask compaction lists: pair = b*128 + i
__device__ int g_active[BB * LL];
__device__ int g_inactive[BB * LL];
__device__ int g_nactive;

// ---------------------------------------------------------------------------
// Kernel 1: Gram matrices. grid (32, B). 256 threads. 16 rows per block.
// Block (0,0) additionally compacts the mask into active/inactive lists.
// ---------------------------------------------------------------------------
__global__ __launch_bounds__(256) void gram_kernel(
    const float* __restrict__ Q, const float* __restrict__ V,
    const int* __restrict__ mask)
{
    int t = threadIdx.x;

    if (blockIdx.x == 0 && blockIdx.y == 0) {
        __shared__ int cA, cI;
        if (t == 0) { cA = 0; cI = 0; }
        __syncthreads();
        for (int e = t; e < BB * LL; e += 256) {
            if (mask[e]) g_active[atomicAdd(&cA, 1)] = e;
            else         g_inactive[atomicAdd(&cI, 1)] = e;
        }
        __syncthreads();
        if (t == 0) g_nactive = cA;
    }

    int b    = blockIdx.y;
    int type = blockIdx.x >> 3;       // 0..3
    int rq   = blockIdx.x & 7;        // 0..7
    const float* A  = ((type & 1) ? V : Q) + (size_t)b * LL * DD;
    const float* Bm = ((type < 2) ? V : Q) + (size_t)b * LL * DD;
    int r0 = rq * 16;

    __shared__ float sA[16 * 65];
    __shared__ float sB[128 * 65];

    float acc[2][4] = {};

    for (int dc = 0; dc < DD; dc += 64) {
        #pragma unroll
        for (int u = 0; u < 32; u++) {
            int idx = t + u * 256;               // 0..8191
            int r = idx >> 6, d = idx & 63;
            sB[r * 65 + d] = Bm[r * DD + dc + d];
        }
        #pragma unroll
        for (int u = 0; u < 4; u++) {
            int idx = t + u * 256;               // 0..1023
            int r = idx >> 6, d = idx & 63;
            sA[r * 65 + d] = A[(r0 + r) * DD + dc + d];
        }
        __syncthreads();

        int rg = t >> 5, kg = t & 31;
        const float* sAr = sA + rg * 2 * 65;
        const float* sBr = sB + kg * 4 * 65;
        #pragma unroll 8
        for (int d = 0; d < 64; d++) {
            float av[2], bv[4];
            #pragma unroll
            for (int a = 0; a < 2; a++) av[a] = sAr[a * 65 + d];
            #pragma unroll
            for (int c = 0; c < 4; c++) bv[c] = sBr[c * 65 + d];
            #pragma unroll
            for (int a = 0; a < 2; a++)
                #pragma unroll
                for (int c = 0; c < 4; c++)
                    acc[a][c] = fmaf(av[a], bv[c], acc[a][c]);
        }
        __syncthreads();
    }

    int rg = t >> 5, kg = t & 31;
    float* G = g_gram + (size_t)(b * 4 + type) * LL * LL;
    bool doMask = (type == 0) || (type == 2);
    #pragma unroll
    for (int a = 0; a < 2; a++) {
        #pragma unroll
        for (int c = 0; c < 4; c++) {
            int k = kg * 4 + c;
            float val = 0.5f * acc[a][c];
            if (doMask && mask[b * LL + k] == 0) val = -1e30f;
            G[(r0 + rg * 2 + a) * LL + k] = val;
        }
    }
}

// ---------------------------------------------------------------------------
// mma.sync / ldmatrix helpers
// ---------------------------------------------------------------------------
__device__ __forceinline__ void mma_bf16(float* c, const uint32_t* a,
                                         uint32_t b0, uint32_t b1)
{
    asm volatile(
        "mma.sync.aligned.m16n8k16.row.col.f32.bf16.bf16.f32 "
        "{%0,%1,%2,%3}, {%4,%5,%6,%7}, {%8,%9}, {%0,%1,%2,%3};"
        : "+f"(c[0]), "+f"(c[1]), "+f"(c[2]), "+f"(c[3])
        : "r"(a[0]), "r"(a[1]), "r"(a[2]), "r"(a[3]), "r"(b0), "r"(b1));
}
__device__ __forceinline__ void ldsm_x4(uint32_t* r, uint32_t addr)
{
    asm volatile("ldmatrix.sync.aligned.m8n8.x4.shared.b16 {%0,%1,%2,%3}, [%4];"
        : "=r"(r[0]), "=r"(r[1]), "=r"(r[2]), "=r"(r[3]) : "r"(addr));
}
__device__ __forceinline__ void ldsm_x4_t(uint32_t* r, uint32_t addr)
{
    asm volatile("ldmatrix.sync.aligned.m8n8.x4.trans.shared.b16 {%0,%1,%2,%3}, [%4];"
        : "=r"(r[0]), "=r"(r[1]), "=r"(r[2]), "=r"(r[3]) : "r"(addr));
}

// ---------------------------------------------------------------------------
// Kernel 2: attention via mma.sync bf16x3 + LayerNorm.
// One block per (b,i), 512 threads, warp tile 32j x 32d.
// Macro-iteration = 128 j x 128 d (two 64-d V halves resident).
// P planes [128 j][136 k] bf16 (hi/lo); V halves [128 k][72 d] bf16 K-major.
// ---------------------------------------------------------------------------
#define NT 512
#define PSTR 136
#define VSTR 72
// byte offsets in dynamic smem
#define OB_PHI   0                     // 128*136*2 = 34816
#define OB_PLO   34816                 // 34816
#define OB_V     69632                 // 4 x 18432 = 73728  [half][plane]
#define VPL      18432                 // bytes per V plane
#define OB_G1    143360                // 128 f
#define OB_G1Q   143872                // 128 f
#define OB_W     144384                // 512 f
#define OB_BI    146432                // 512 f
#define OB_ST1   148480                // 128*4 f
#define OB_ST2   150528                // 128*4 f
#define OB_MU    152576                // 128 f
#define OB_RS    153088                // 128 f
#define SMEM_BYTES 153600

__global__ __launch_bounds__(NT, 1) void attn_kernel(
    const float* __restrict__ Q, const float* __restrict__ V,
    const float* __restrict__ nw, const float* __restrict__ nb,
    float* __restrict__ out)
{
    int bid = blockIdx.x;
    int t   = threadIdx.x;
    int nA  = g_nactive;
    bool active = (bid < nA);
    int pair = active ? g_active[bid] : g_inactive[bid - nA];
    int b = pair >> 7, i = pair & 127;
    float* outBase = out + ((size_t)(b * LL + i)) * LL * TWO_D; // [128 j][512 d]

    if (!active) {
        float4 z = make_float4(0.f, 0.f, 0.f, 0.f);
        float4* o4 = (float4*)outBase;
        #pragma unroll
        for (int u = 0; u < 32; u++) o4[t + u * NT] = z;
        return;
    }

    extern __shared__ char smc[];
    uint32_t smb = (uint32_t)__cvta_generic_to_shared(smc);

    __nv_bfloat16* sPhi = (__nv_bfloat16*)(smc + OB_PHI);
    __nv_bfloat16* sPlo = (__nv_bfloat16*)(smc + OB_PLO);
    float* sG1  = (float*)(smc + OB_G1);
    float* sG1q = (float*)(smc + OB_G1Q);
    float* sW   = (float*)(smc + OB_W);
    float* sBi  = (float*)(smc + OB_BI);
    float* sST1 = (float*)(smc + OB_ST1);
    float* sST2 = (float*)(smc + OB_ST2);
    float* sMu  = (float*)(smc + OB_MU);
    float* sRs  = (float*)(smc + OB_RS);

    const float* G   = g_gram + (size_t)b * 4 * LL * LL;
    const float* G2  = G + 1 * LL * LL;   // 0.5*V.V^T (unmasked)
    const float* G2q = G + 3 * LL * LL;   // 0.5*V.Q^T (unmasked)
    const float* QB = Q + (size_t)b * LL * DD;
    const float* VB = V + (size_t)b * LL * DD;

    int warp = t >> 5, lane = t & 31;
    int g  = lane >> 2;      // 0..7
    int tq = lane & 3;       // 0..3
    int jg     = warp >> 2;         // 0..3 -> 32 j rows
    int dgroup = warp & 3;          // 0..3 -> 32 d cols within 128-d macro
    int mbase = jg * 32;

    // ldmatrix lane addressing (mat = lane>>3, mr = lane&7)
    int mat = lane >> 3, mr = lane & 7;
    uint32_t aAddrH = smb + OB_PHI +
        (uint32_t)(((mbase + (mat & 1) * 8 + mr) * PSTR + (mat >> 1) * 8) * 2);
    uint32_t aAddrL = aAddrH + (OB_PLO - OB_PHI);
    // B: half = dgroup>>1, within-half d offset = (dgroup&1)*32
    uint32_t bBase = smb + OB_V + (uint32_t)((dgroup >> 1) * (2 * VPL)) +
        (uint32_t)((((mat & 1) * 8 + mr) * VSTR + (dgroup & 1) * 32 + (mat >> 1) * 8) * 2);

    if (t < 128) {
        sG1[t]  = G[i * LL + t];                 // masked 0.5*q_i . v_k
        sG1q[t] = G[2 * LL * LL + i * LL + t];   // masked 0.5*q_i . q_k
    }
    sW[t]  = nw[t];
    sBi[t] = nb[t];

    // half-tile (64 d) prefetch: 8 float2 per thread
    float2 pf[8];
    auto prefetch_half = [&](const float* src, int dbase) {
        #pragma unroll
        for (int u = 0; u < 8; u++) {
            int idx = t + u * NT;            // 0..4095
            int k = idx >> 5, dp = idx & 31;
            pf[u] = *(const float2*)&src[k * DD + dbase + dp * 2];
        }
    };
    auto store_half = [&](int half, const float2* srcv) {
        uint32_t* vhi = (uint32_t*)(smc + OB_V + half * 2 * VPL);
        uint32_t* vlo = (uint32_t*)(smc + OB_V + half * 2 * VPL + VPL);
        #pragma unroll
        for (int u = 0; u < 8; u++) {
            int idx = t + u * NT;
            int k = idx >> 5, dp = idx & 31;
            float x = srcv[u].x, y = srcv[u].y;
            __nv_bfloat162 h2 = __floats2bfloat162_rn(x, y);
            float rx = x - __bfloat162float(h2.x);
            float ry = y - __bfloat162float(h2.y);
            __nv_bfloat162 l2 = __floats2bfloat162_rn(rx, ry);
            int w = k * (VSTR / 2) + dp;
            vhi[w] = *(uint32_t*)&h2;
            vlo[w] = *(uint32_t*)&l2;
        }
    };
    auto direct_half = [&](int half, const float* src, int dbase) {
        uint32_t* vhi = (uint32_t*)(smc + OB_V + half * 2 * VPL);
        uint32_t* vlo = (uint32_t*)(smc + OB_V + half * 2 * VPL + VPL);
        #pragma unroll
        for (int u = 0; u < 8; u++) {
            int idx = t + u * NT;
            int k = idx >> 5, dp = idx & 31;
            float2 v2 = *(const float2*)&src[k * DD + dbase + dp * 2];
            __nv_bfloat162 h2 = __floats2bfloat162_rn(v2.x, v2.y);
            float rx = v2.x - __bfloat162float(h2.x);
            float ry = v2.y - __bfloat162float(h2.y);
            __nv_bfloat162 l2 = __floats2bfloat162_rn(rx, ry);
            int w = k * (VSTR / 2) + dp;
            vhi[w] = *(uint32_t*)&h2;
            vlo[w] = *(uint32_t*)&l2;
        }
    };

    auto softmax_side = [&](const float* Grow, const float* g1) {
        for (int jj = warp; jj < 128; jj += 16) {
            const float* r = Grow + jj * LL;
            float s0 = g1[lane]      + r[lane];
            float s1 = g1[lane + 32] + r[lane + 32];
            float s2 = g1[lane + 64] + r[lane + 64];
            float s3 = g1[lane + 96] + r[lane + 96];
            float m = fmaxf(fmaxf(s0, s1), fmaxf(s2, s3));
            #pragma unroll
            for (int o = 16; o; o >>= 1) m = fmaxf(m, __shfl_xor_sync(0xffffffffu, m, o));
            float e0 = __expf(s0 - m), e1 = __expf(s1 - m);
            float e2 = __expf(s2 - m), e3 = __expf(s3 - m);
            float su = e0 + e1 + e2 + e3;
            #pragma unroll
            for (int o = 16; o; o >>= 1) su += __shfl_xor_sync(0xffffffffu, su, o);
            float inv = 1.0f / su;
            float vals[4] = {e0 * inv, e1 * inv, e2 * inv, e3 * inv};
            #pragma unroll
            for (int c = 0; c < 4; c++) {
                int k = lane + c * 32;
                float x = vals[c];
                __nv_bfloat16 h = __float2bfloat16(x);
                __nv_bfloat16 l = __float2bfloat16(x - __bfloat162float(h));
                sPhi[jj * PSTR + k] = h;
                sPlo[jj * PSTR + k] = l;
            }
        }
    };

    // ---- prologue: prefetch macro0 half0, softmax side0, stage V halves ----
    prefetch_half(VB, 0);
    __syncthreads();                 // sG1/sG1q/sW/sBi visible
    softmax_side(G2, sG1);
    store_half(0, pf);
    direct_half(1, VB, 64);
    __syncthreads();

    float ls1[4] = {}, ls2[4] = {};

    // ---- 4 macro-iterations: (s, dp) over 128j x 128d each ----
    #pragma unroll 1
    for (int mi = 0; mi < 4; mi++) {
        int s  = mi >> 1;
        int dp = mi & 1;

        // prefetch half0 of next macro (gmem loads fly during MMA)
        if (mi < 3) {
            int nx = mi + 1;
            const float* nsrc = (nx >> 1) ? QB : VB;
            prefetch_half(nsrc, (nx & 1) * 128);
        }

        // ---- MMA: warp tile 32j x 32d, k = 128 ----
        float acc[2][4][4] = {};
        #pragma unroll
        for (int kt = 0; kt < 8; kt++) {
            uint32_t ah0[4], ah1[4], al0[4], al1[4];
            uint32_t bh0[4], bh1[4], bl0[4], bl1[4];
            uint32_t ka = (uint32_t)(kt * 32);
            uint32_t kb = (uint32_t)(kt * 16 * VSTR * 2);
            ldsm_x4(ah0, aAddrH + ka);
            ldsm_x4(ah1, aAddrH + 16 * PSTR * 2 + ka);
            ldsm_x4(al0, aAddrL + ka);
            ldsm_x4(al1, aAddrL + 16 * PSTR * 2 + ka);
            ldsm_x4_t(bh0, bBase + kb);
            ldsm_x4_t(bh1, bBase + kb + 32);
            ldsm_x4_t(bl0, bBase + VPL + kb);
            ldsm_x4_t(bl1, bBase + VPL + kb + 32);
            // hi*hi
            mma_bf16(acc[0][0], ah0, bh0[0], bh0[1]);
            mma_bf16(acc[0][1], ah0, bh0[2], bh0[3]);
            mma_bf16(acc[0][2], ah0, bh1[0], bh1[1]);
            mma_bf16(acc[0][3], ah0, bh1[2], bh1[3]);
            mma_bf16(acc[1][0], ah1, bh0[0], bh0[1]);
            mma_bf16(acc[1][1], ah1, bh0[2], bh0[3]);
            mma_bf16(acc[1][2], ah1, bh1[0], bh1[1]);
            mma_bf16(acc[1][3], ah1, bh1[2], bh1[3]);
            // hi*lo
            mma_bf16(acc[0][0], ah0, bl0[0], bl0[1]);
            mma_bf16(acc[0][1], ah0, bl0[2], bl0[3]);
            mma_bf16(acc[0][2], ah0, bl1[0], bl1[1]);
            mma_bf16(acc[0][3], ah0, bl1[2], bl1[3]);
            mma_bf16(acc[1][0], ah1, bl0[0], bl0[1]);
            mma_bf16(acc[1][1], ah1, bl0[2], bl0[3]);
            mma_bf16(acc[1][2], ah1, bl1[0], bl1[1]);
            mma_bf16(acc[1][3], ah1, bl1[2], bl1[3]);
            // lo*hi
            mma_bf16(acc[0][0], al0, bh0[0], bh0[1]);
            mma_bf16(acc[0][1], al0, bh0[2], bh0[3]);
            mma_bf16(acc[0][2], al0, bh1[0], bh1[1]);
            mma_bf16(acc[0][3], al0, bh1[2], bh1[3]);
            mma_bf16(acc[1][0], al1, bh0[0], bh0[1]);
            mma_bf16(acc[1][1], al1, bh0[2], bh0[3]);
            mma_bf16(acc[1][2], al1, bh1[0], bh1[1]);
            mma_bf16(acc[1][3], al1, bh1[2], bh1[3]);
        }

        // ---- store raw output + accumulate LN stats ----
        int colb = s * 256 + dp * 128 + dgroup * 32;
        #pragma unroll
        for (int mt = 0; mt < 2; mt++)
            #pragma unroll
            for (int nt = 0; nt < 4; nt++) {
                const float* a4 = acc[mt][nt];
                int r0 = mbase + mt * 16 + g;
                int c0 = colb + nt * 8 + tq * 2;
                *(float2*)&outBase[(size_t)r0 * TWO_D + c0] =
                    make_float2(a4[0], a4[1]);
                *(float2*)&outBase[(size_t)(r0 + 8) * TWO_D + c0] =
                    make_float2(a4[2], a4[3]);
                ls1[mt * 2 + 0] += a4[0] + a4[1];
                ls2[mt * 2 + 0] = fmaf(a4[0], a4[0], fmaf(a4[1], a4[1], ls2[mt * 2 + 0]));
                ls1[mt * 2 + 1] += a4[2] + a4[3];
                ls2[mt * 2 + 1] = fmaf(a4[2], a4[2], fmaf(a4[3], a4[3], ls2[mt * 2 + 1]));
            }
        __syncthreads();          // V halves + P free to overwrite

        if (mi == 1) softmax_side(G2q, sG1q);   // rewrite P for side 1
        if (mi < 3) {
            store_half(0, pf);
            int nx = mi + 1;
            const float* nsrc = (nx >> 1) ? QB : VB;
            direct_half(1, nsrc, (nx & 1) * 128 + 64);
            __syncthreads();
        }
    }

    // ---- LN stats: shfl-reduce across quad lanes, then smem reduce ----
    #pragma unroll
    for (int ss = 0; ss < 4; ss++) {
        float v1 = ls1[ss], v2 = ls2[ss];
        v1 += __shfl_xor_sync(0xffffffffu, v1, 1);
        v1 += __shfl_xor_sync(0xffffffffu, v1, 2);
        v2 += __shfl_xor_sync(0xffffffffu, v2, 1);
        v2 += __shfl_xor_sync(0xffffffffu, v2, 2);
        if (tq == 0) {
            int row = mbase + (ss >> 1) * 16 + (ss & 1) * 8 + g;
            sST1[row * 4 + dgroup] = v1;
            sST2[row * 4 + dgroup] = v2;
        }
    }
    __syncthreads();
    if (t < 128) {
        float a1 = sST1[t * 4 + 0] + sST1[t * 4 + 1] + sST1[t * 4 + 2] + sST1[t * 4 + 3];
        float a2 = sST2[t * 4 + 0] + sST2[t * 4 + 1] + sST2[t * 4 + 2] + sST2[t * 4 + 3];
        float mu  = a1 * (1.0f / 512.0f);
        float var = a2 * (1.0f / 512.0f) - mu * mu;
        sMu[t] = mu;
        sRs[t] = rsqrtf(var + 1e-5f);
    }
    __syncthreads();

    // ---- Phase C: LayerNorm in place (region is L2-hot) ----
    int jr = t >> 2, part = t & 3;
    float mu = sMu[jr], rs = sRs[jr];
    float* orow = outBase + (size_t)jr * TWO_D;
    #pragma unroll 4
    for (int itc = 0; itc < 32; itc++) {
        int idx4 = itc * 4 + part;       // 0..127
        int d = idx4 * 4;
        float4 x = *(float4*)&orow[d];
        x.x = (x.x - mu) * rs * sW[d + 0] + sBi[d + 0];
        x.y = (x.y - mu) * rs * sW[d + 1] + sBi[d + 1];
        x.z = (x.z - mu) * rs * sW[d + 2] + sBi[d + 2];
        x.w = (x.w - mu) * rs * sW[d + 3] + sBi[d + 3];
        *(float4*)&orow[d] = x;
    }
}

// ---------------------------------------------------------------------------
extern "C" void kernel_launch(void* const* d_in, const int* in_sizes, int n_in,
                              void* d_out, int out_size)
{
    const float* q    = (const float*)d_in[0];
    const float* v    = (const float*)d_in[1];
    const int*   mask = (const int*)d_in[2];
    const float* nw   = (const float*)d_in[3];
    const float* nb   = (const float*)d_in[4];
    float* out = (float*)d_out;

    gram_kernel<<<dim3(32, BB), 256>>>(q, v, mask);

    cudaFuncSetAttribute(attn_kernel,
                         cudaFuncAttributeMaxDynamicSharedMemorySize, SMEM_BYTES);
    attn_kernel<<<BB * LL, NT, SMEM_BYTES>>>(q, v, nw, nb, out);
}